// round 15
// baseline (speedup 1.0000x reference)
#include <cuda_runtime.h>
#include <cuda_bf16.h>
#include <math.h>

// ---------------- constants ----------------
#define NSPEC 5456
#define PI_F 3.14159265358979323846f

__constant__ int c_OFF[17] = {0,1,10,35,84,165,286,455,680,969,1330,1771,2300,2925,3654,4495,5456};
// prefix of canonical-row counts per l:  cnt(l) = 2l^2+2l+1
__constant__ int c_POFF[17] = {0,1,6,19,44,85,146,231,344,489,670,891,1156,1469,1834,2255,2736};

// log(n!) for n = 0..31 (double; needed for cancellation-heavy Wigner coefficients)
__constant__ double c_LFD[32] = {
    0.0, 0.0, 0.6931471805599453, 1.791759469228055,
    3.1780538303479458, 4.787491742782046, 6.579251212010101, 8.525161361065415,
    10.60460290274525, 12.801827480081469, 15.104412573075516, 17.502307845873887,
    19.987214495661885, 22.552163853123425, 25.19122118273868, 27.89927138384089,
    30.671860106080672, 33.50507345013689, 36.39544520803305, 39.339884187199495,
    42.335616460753485, 45.38013889847691, 48.47118135183523, 51.60667556776438,
    54.78472939811232, 58.00360522298052, 61.261701761002, 64.55753862700634,
    67.88974313718154, 71.25703896716801, 74.65823978744394, 78.09222699192909
};

typedef unsigned long long u64;

// ---------------- f32x2 packed helpers ----------------
__device__ __forceinline__ u64 pk(float lo, float hi) {
    u64 r; asm("mov.b64 %0,{%1,%2};" : "=l"(r) : "f"(lo), "f"(hi)); return r;
}
__device__ __forceinline__ u64 fma2(u64 a, u64 b, u64 c) {
    u64 r; asm("fma.rn.f32x2 %0,%1,%2,%3;" : "=l"(r) : "l"(a), "l"(b), "l"(c)); return r;
}
__device__ __forceinline__ u64 add2(u64 a, u64 b) {
    u64 r; asm("add.rn.f32x2 %0,%1,%2;" : "=l"(r) : "l"(a), "l"(b)); return r;
}
__device__ __forceinline__ void upk(u64 v, float& lo, float& hi) {
    asm("mov.b64 {%0,%1},%2;" : "=f"(lo), "=f"(hi) : "l"(v));
}

// ---------------- scratch (static device globals; no allocation) ----------------
__device__ float2 g_T1[8388608];     // [bf=128][m=16][j=64][c=64]   (m >= 0 only)
__device__ float2 g_T2[7872512];     // [mi=31][ni=31][j=64][bf=128] (only mi>=15 written)
__device__ float  g_Wan[NSPEC*64];
__device__ float  g_Wsy[NSPEC*32];
__device__ float2 g_D[NSPEC*72];
__device__ float  g_wquad[64];
__device__ float  g_KT[72*512];
__device__ float  g_tw32C[512];      // [i<16][j<32] cos(i*j*pi/32)
__device__ float  g_tw32S[512];
__device__ float  g_tw16C[256];      // [i<16][j<16] cos(i*j*pi/16)
__device__ float  g_tw16S[256];
__device__ float2 g_xc[NSPEC*128];   // [s][b*16+f]   (only m>=0 rows written)
__device__ float2 g_yc[NSPEC*512];   // [s][i*32+o]
__device__ float2 g_zc[NSPEC*256];   // [s][b*32+o]   (only canonical s written)
__device__ float2 g_Zsum[7872512];   // [mi=31][ni=31][j=32][bo=256]  (only ni>=15 written)
__device__ float2 g_U1[8126464];     // [a=32][ni=31][j=32][bo=256]   (only ni>=15 written)

// ---------------- init: KT, quad weights, twiddle tables ----------------
__global__ void k_init(const float* __restrict__ ker) {
    int idx = blockIdx.x * blockDim.x + threadIdx.x;
    if (idx < 36864) {
        int g  = idx >> 9;
        int io = idx & 511;
        g_KT[idx] = ker[io * 72 + g] * (1.0f / 12.0f);
    }
    if (idx < 512) {
        int i = idx >> 5, j = idx & 31;
        float sv, cv; sincosf(0.0981747704f * (float)(i * j), &sv, &cv);  // pi/32
        g_tw32C[idx] = cv; g_tw32S[idx] = sv;
    }
    if (idx < 256) {
        int i = idx >> 4, j = idx & 15;
        float sv, cv; sincosf(0.1963495408f * (float)(i * j), &sv, &cv);  // pi/16
        g_tw16C[idx] = cv; g_tw16S[idx] = sv;
    }
    if (idx < 64) {
        int j = idx;
        float inner = 0.0f;
        for (int k = 0; k < 32; k++)
            inner += sinf((float)((2*j+1)*(2*k+1)) * PI_F / 128.0f) / (float)(2*k+1);
        float w = (2.0f / 32.0f) * sinf(PI_F * (float)(2*j+1) / 128.0f) * inner;
        g_wquad[j] = w / 4096.0f;
    }
}

// ---------------- Wigner tables: canonical (M,N) only; mirrors written via symmetry --------
__global__ void k_wigner(const float* __restrict__ ge) {
    int s = blockIdx.x;
    __shared__ float lcoef[32];
    int t = threadIdx.x;
    int l = 0;
    #pragma unroll
    for (int i = 1; i < 16; i++) l += (c_OFF[i] <= s) ? 1 : 0;
    int dsz = 2*l + 1;
    int rem = s - c_OFF[l];
    int M = rem / dsz - l;
    int N = rem % dsz - l;
    if (!(M > 0 || (M == 0 && N >= 0))) return;   // non-canonical: mirror handles it
    int smir = c_OFF[l] + (l - M) * dsz + (l - N);
    float sg = ((M - N) & 1) ? -1.0f : 1.0f;
    int Kmin = (M - N) > 0 ? (M - N) : 0;
    int Kmax = (l + M) < (l - N) ? (l + M) : (l - N);
    if (t < 32 && t >= Kmin && t <= Kmax) {
        double lgA = 0.5 * (c_LFD[l+M] + c_LFD[l-M] + c_LFD[l+N] + c_LFD[l-N]);
        lcoef[t] = (float)(lgA - (c_LFD[t] + c_LFD[l+M-t] + c_LFD[l-N-t] + c_LFD[N-M+t]));
    }
    __syncthreads();
    if (t >= 168) return;
    float beta;
    if (t < 64)       beta = PI_F * (float)(2*t + 1) / 128.0f;
    else if (t < 96)  beta = PI_F * (float)(2*(t-64) + 1) / 64.0f;
    else              beta = ge[(t - 96) * 3 + 1];
    float ch  = __cosf(0.5f * beta);
    float shv = __sinf(0.5f * beta);
    float lc  = __logf(ch);
    float lsn = __logf(shv);
    float dval = 0.0f;
    for (int K = Kmin; K <= Kmax; K++) {
        int e1 = 2*l + M - N - 2*K;
        int e2 = N - M + 2*K;
        float arg = lcoef[K];
        if (e1) arg += (float)e1 * lc;
        if (e2) arg += (float)e2 * lsn;
        float term = __expf(arg);
        dval += (K & 1) ? -term : term;
    }
    if (t < 64) {
        float wv = dval * g_wquad[t];
        g_Wan[s * 64 + t] = wv;
        if (M == 0 && s != smir)
            g_Wan[smir * 64 + t] = sg * wv;
    } else if (t < 96) {
        float wv = dval * (float)(2*l + 1);
        g_Wsy[s * 32 + (t - 64)] = wv;
        if (s != smir) g_Wsy[smir * 32 + (t - 64)] = sg * wv;
    } else {
        int g = t - 96;
        float alpha = ge[g*3 + 0], gamma = ge[g*3 + 2];
        float th = (float)M * alpha + (float)N * gamma;
        float sv, cv; __sincosf(th, &sv, &cv);
        float2 Dv = make_float2(dval * cv, -dval * sv);
        g_D[s * 72 + g] = Dv;
        if (s != smir) g_D[smir * 72 + g] = make_float2(sg * Dv.x, -sg * Dv.y);
    }
}

// ---------------- Stage A: DFT over first axis, a-folded; 2 j per block ----------------
// block per (bf, jp): 4096 blocks x 256 threads = (c 0..63) x (m0 0..3); j = jp*2 + {0,1}
__global__ void k_dftA(const float* __restrict__ x) {
    __shared__ __align__(16) float sxu[2][64 * 36];
    __shared__ __align__(16) float sxv[2][64 * 36];
    __shared__ __align__(16) float twC[16 * 32];
    __shared__ __align__(16) float twS[16 * 32];
    int bid = blockIdx.x;
    int jp = bid & 31, bf = bid >> 5;
    int j0 = jp * 2;
    int tid = threadIdx.x;
    const float* xb = x + bf * 262144 + j0 * 64;
    for (int idx = tid; idx < 4096; idx += 256) {
        int jj = idx >> 11;          // 0..1
        int a  = (idx >> 6) & 31;
        int c  = idx & 63;
        float xa  = xb[a * 4096 + jj * 64 + c];
        float xc2 = xb[(a + 32) * 4096 + jj * 64 + c];
        sxu[jj][c * 36 + a] = xa + xc2;
        sxv[jj][c * 36 + a] = xa - xc2;
    }
    for (int idx = tid; idx < 512; idx += 256) {
        twC[idx] = g_tw32C[idx];
        twS[idx] = g_tw32S[idx];
    }
    __syncthreads();
    int c = tid & 63, m0 = tid >> 6;
    u64 aC0[4] = {0,0,0,0}, aS0[4] = {0,0,0,0};
    u64 aC1[4] = {0,0,0,0}, aS1[4] = {0,0,0,0};
    for (int a0 = 0; a0 < 32; a0 += 4) {
        ulonglong2 U0 = *(const ulonglong2*)&sxu[0][c * 36 + a0];
        ulonglong2 V0 = *(const ulonglong2*)&sxv[0][c * 36 + a0];
        ulonglong2 U1 = *(const ulonglong2*)&sxu[1][c * 36 + a0];
        ulonglong2 V1 = *(const ulonglong2*)&sxv[1][c * 36 + a0];
        #pragma unroll
        for (int it = 0; it < 4; it++) {
            int m = m0 * 4 + it;
            ulonglong2 TC = *(const ulonglong2*)&twC[m * 32 + a0];
            ulonglong2 TS = *(const ulonglong2*)&twS[m * 32 + a0];
            u64 x0lo = (it & 1) ? V0.x : U0.x;
            u64 x0hi = (it & 1) ? V0.y : U0.y;
            u64 x1lo = (it & 1) ? V1.x : U1.x;
            u64 x1hi = (it & 1) ? V1.y : U1.y;
            aC0[it] = fma2(x0lo, TC.x, aC0[it]);
            aC0[it] = fma2(x0hi, TC.y, aC0[it]);
            aS0[it] = fma2(x0lo, TS.x, aS0[it]);
            aS0[it] = fma2(x0hi, TS.y, aS0[it]);
            aC1[it] = fma2(x1lo, TC.x, aC1[it]);
            aC1[it] = fma2(x1hi, TC.y, aC1[it]);
            aS1[it] = fma2(x1lo, TS.x, aS1[it]);
            aS1[it] = fma2(x1hi, TS.y, aS1[it]);
        }
    }
    #pragma unroll
    for (int it = 0; it < 4; it++) {
        int m = m0 * 4 + it;
        float c1, c2, s1, s2;
        upk(aC0[it], c1, c2); upk(aS0[it], s1, s2);
        g_T1[bf * 65536 + m * 4096 + j0 * 64 + c] = make_float2(c1 + c2, -(s1 + s2));
        upk(aC1[it], c1, c2); upk(aS1[it], s1, s2);
        g_T1[bf * 65536 + m * 4096 + (j0 + 1) * 64 + c] = make_float2(c1 + c2, -(s1 + s2));
    }
}

// ---------------- Stage C: DFT over third axis; ONLY mi >= 15 (m >= 0) ----
// grid: (mi-15)*128 + j*2 + bfh = 2048 blocks x 256 threads
__global__ void k_dftC() {
    __shared__ __align__(16) float suX[64 * 36];
    __shared__ __align__(16) float suY[64 * 36];
    __shared__ __align__(16) float svX[64 * 36];
    __shared__ __align__(16) float svY[64 * 36];
    __shared__ __align__(16) float twQC[16 * 32];
    __shared__ __align__(16) float twQS[16 * 32];
    int bid = blockIdx.x;
    int mi  = 15 + (bid >> 7);
    int j   = (bid >> 1) & 63;
    int bf0 = (bid & 1) * 64;
    int m = mi - 15;
    int tid = threadIdx.x;
    for (int idx = tid; idx < 2048; idx += 256) {
        int bfl = idx >> 5, c = idx & 31;
        const float2* p = &g_T1[(bf0 + bfl) * 65536 + m * 4096 + j * 64];
        float2 a = p[c];
        float2 b = p[c + 32];
        suX[bfl * 36 + c] = a.x + b.x;
        svX[bfl * 36 + c] = a.x - b.x;
        suY[bfl * 36 + c] = a.y + b.y;
        svY[bfl * 36 + c] = a.y - b.y;
    }
    for (int idx = tid; idx < 512; idx += 256) {
        twQC[idx] = g_tw32C[idx];
        twQS[idx] = g_tw32S[idx];
    }
    __syncthreads();
    int bfl = tid & 63, q0 = tid >> 6;
    const float* sX = (q0 & 1) ? svX : suX;
    const float* sY = (q0 & 1) ? svY : suY;
    u64 A[16];
    #pragma unroll
    for (int i = 0; i < 16; i++) A[i] = 0ULL;
    for (int c0 = 0; c0 < 32; c0 += 4) {
        ulonglong2 X = *(const ulonglong2*)&sX[bfl * 36 + c0];
        ulonglong2 Y = *(const ulonglong2*)&sY[bfl * 36 + c0];
        #pragma unroll
        for (int it = 0; it < 4; it++) {
            int q = q0 + 4 * it;
            ulonglong2 TC = *(const ulonglong2*)&twQC[q * 32 + c0];
            ulonglong2 TS = *(const ulonglong2*)&twQS[q * 32 + c0];
            A[it*4+0] = fma2(X.x, TC.x, A[it*4+0]);
            A[it*4+0] = fma2(X.y, TC.y, A[it*4+0]);
            A[it*4+1] = fma2(X.x, TS.x, A[it*4+1]);
            A[it*4+1] = fma2(X.y, TS.y, A[it*4+1]);
            A[it*4+2] = fma2(Y.x, TC.x, A[it*4+2]);
            A[it*4+2] = fma2(Y.y, TC.y, A[it*4+2]);
            A[it*4+3] = fma2(Y.x, TS.x, A[it*4+3]);
            A[it*4+3] = fma2(Y.y, TS.y, A[it*4+3]);
        }
    }
    #pragma unroll
    for (int it = 0; it < 4; it++) {
        int q = q0 + 4 * it;
        float a1, a2;
        float Sxc, SxS, Syc, SyS;
        upk(A[it*4+0], a1, a2); Sxc = a1 + a2;
        upk(A[it*4+1], a1, a2); SxS = a1 + a2;
        upk(A[it*4+2], a1, a2); Syc = a1 + a2;
        upk(A[it*4+3], a1, a2); SyS = a1 + a2;
        g_T2[((mi * 31 + (15 + q)) * 64 + j) * 128 + bf0 + bfl] =
            make_float2(Sxc + SyS, Syc - SxS);
        if (q > 0)
            g_T2[((mi * 31 + (15 - q)) * 64 + j) * 128 + bf0 + bfl] =
                make_float2(Sxc - SyS, Syc + SxS);
    }
}

// ---------------- xc: ONLY mi >= 15; block per (mi,ni) ----------------
__global__ void k_xc() {
    int mi = 15 + blockIdx.x / 31, ni = blockIdx.x % 31;
    int m = mi - 15, n = ni - 15;
    int an = n < 0 ? -n : n;
    int lmin = m > an ? m : an;
    int nl = 16 - lmin;
    __shared__ float ws[16 * 64];
    __shared__ int srow[16];
    int tid = threadIdx.x;
    if (tid < nl) {
        int l = lmin + tid;
        srow[tid] = c_OFF[l] + (m + l) * (2*l + 1) + (n + l);
    }
    __syncthreads();
    for (int idx = tid; idx < nl * 64; idx += 128)
        ws[idx] = g_Wan[srow[idx >> 6] * 64 + (idx & 63)];
    __syncthreads();
    u64 acc[16];
    #pragma unroll
    for (int i = 0; i < 16; i++) acc[i] = 0ULL;
    const float2* src = &g_T2[(mi * 31 + ni) * 8192 + tid];
    for (int j = 0; j < 64; j++) {
        float2 v = src[j * 128];
        u64 vp = pk(v.x, v.y);
        #pragma unroll
        for (int li = 0; li < 16; li++) {
            if (li < nl) {
                float w = ws[li * 64 + j];
                acc[li] = fma2(vp, pk(w, w), acc[li]);
            }
        }
    }
    #pragma unroll
    for (int li = 0; li < 16; li++) {
        if (li < nl) {
            float lo, hi; upk(acc[li], lo, hi);
            g_xc[srow[li] * 128 + tid] = make_float2(lo, hi);
        }
    }
}

// ---------------- yc: canonical rows only (compact grid) + mirror writes ----------------
// yc(mirror) = sg * conj(yc).  grid 684 blocks x 512 threads; 4 canonical rows per block.
__global__ void k_yc() {
    __shared__ __align__(16) float2 ds[4 * 72];
    __shared__ int   sS[4], sMir[4];
    __shared__ float sSg[4];
    int t = threadIdx.x;
    if (t < 4) {
        int cs = blockIdx.x * 4 + t;
        int l = 0;
        #pragma unroll
        for (int i = 1; i < 16; i++) l += (c_POFF[i] <= cs) ? 1 : 0;
        int r = cs - c_POFF[l];
        int d = 2 * l + 1;
        int M, N;
        if (r <= l) { M = 0; N = r; }
        else { int rr = r - (l + 1); M = rr / d + 1; N = rr % d - l; }
        sS[t]   = c_OFF[l] + (M + l) * d + (N + l);
        sMir[t] = c_OFF[l] + (l - M) * d + (l - N);
        sSg[t]  = ((M - N) & 1) ? -1.0f : 1.0f;
    }
    __syncthreads();
    if (t < 288) {
        int row = t / 72, g = t % 72;
        ds[t] = g_D[sS[row] * 72 + g];
    }
    __syncthreads();
    u64 a0 = 0ULL, a1 = 0ULL, a2 = 0ULL, a3 = 0ULL;
    #pragma unroll 4
    for (int g = 0; g < 72; g++) {
        float k = g_KT[g * 512 + t];
        u64 k2 = pk(k, k);
        a0 = fma2(k2, *(const u64*)&ds[g],       a0);
        a1 = fma2(k2, *(const u64*)&ds[72 + g],  a1);
        a2 = fma2(k2, *(const u64*)&ds[144 + g], a2);
        a3 = fma2(k2, *(const u64*)&ds[216 + g], a3);
    }
    u64 accs[4] = {a0, a1, a2, a3};
    #pragma unroll
    for (int row = 0; row < 4; row++) {
        float lo, hi; upk(accs[row], lo, hi);
        int s = sS[row], smir = sMir[row];
        g_yc[s * 512 + t] = make_float2(lo, hi);
        if (smir != s) {
            float sg = sSg[row];
            g_yc[smir * 512 + t] = make_float2(sg * lo, -sg * hi);
        }
    }
}

// ---------------- main block-diagonal complex GEMM: canonical (m,n) only ----------------
__global__ void k_ze() {
    __shared__ __align__(16) unsigned char sraw[49152];
    ulonglong2* xch = (ulonglong2*)sraw;            //  8KB
    ulonglong2* ysh = (ulonglong2*)(sraw + 8192);   // 32KB
    u64*        red = (u64*)sraw;                   //  8KB (reuses xch)
    int s = blockIdx.x;
    int tid = threadIdx.x;
    int w = tid >> 5, lane = tid & 31;
    int bg = lane >> 3, og = lane & 7;
    int l = 0;
    #pragma unroll
    for (int i = 1; i < 16; i++) l += (c_OFF[i] <= s) ? 1 : 0;
    int d = 2 * l + 1;
    int rem = s - c_OFF[l];
    int M = rem / d - l, N = rem % d - l;
    if (!(M > 0 || (M == 0 && N >= 0))) return;
    int xbase = c_OFF[l] + (rem / d) * d;
    int ybase = c_OFF[l] + (rem % d);
    u64 acc[8];
    #pragma unroll
    for (int i = 0; i < 8; i++) acc[i] = 0ULL;
    for (int k0 = 0; k0 < d; k0 += 4) {
        int kc = d - k0; if (kc > 4) kc = 4;
        if (k0) __syncthreads();
        for (int idx = tid; idx < kc * 128; idx += 128) {
            int kk = idx >> 7, r = idx & 127;
            int i = r & 15, b = r >> 4;
            float2 v = g_xc[(xbase + k0 + kk) * 128 + r];
            xch[kk * 128 + i * 8 + b] = make_ulonglong2(pk(v.x, v.x), pk(-v.y, v.y));
        }
        for (int idx = tid; idx < kc * 512; idx += 128) {
            int kk = idx >> 9, t = idx & 511;
            float2 y = g_yc[(ybase + (k0 + kk) * d) * 512 + t];
            ysh[kk * 512 + t] = make_ulonglong2(pk(y.x, y.y), pk(y.y, y.x));
        }
        __syncthreads();
        if (w < kc) {
            const ulonglong2* xr = &xch[w * 128 + bg * 2];
            const ulonglong2* yr = &ysh[w * 512 + og * 4];
            #pragma unroll
            for (int i = 0; i < 16; i++) {
                ulonglong2 X0 = xr[i * 8];
                ulonglong2 X1 = xr[i * 8 + 1];
                ulonglong2 Y0 = yr[i * 32];
                ulonglong2 Y1 = yr[i * 32 + 1];
                ulonglong2 Y2 = yr[i * 32 + 2];
                ulonglong2 Y3 = yr[i * 32 + 3];
                acc[0] = fma2(X0.x, Y0.x, fma2(X0.y, Y0.y, acc[0]));
                acc[1] = fma2(X0.x, Y1.x, fma2(X0.y, Y1.y, acc[1]));
                acc[2] = fma2(X0.x, Y2.x, fma2(X0.y, Y2.y, acc[2]));
                acc[3] = fma2(X0.x, Y3.x, fma2(X0.y, Y3.y, acc[3]));
                acc[4] = fma2(X1.x, Y0.x, fma2(X1.y, Y0.y, acc[4]));
                acc[5] = fma2(X1.x, Y1.x, fma2(X1.y, Y1.y, acc[5]));
                acc[6] = fma2(X1.x, Y2.x, fma2(X1.y, Y2.y, acc[6]));
                acc[7] = fma2(X1.x, Y3.x, fma2(X1.y, Y3.y, acc[7]));
            }
        }
    }
    __syncthreads();
    #pragma unroll
    for (int i = 0; i < 8; i++) red[tid * 8 + i] = acc[i];
    __syncthreads();
    #pragma unroll
    for (int rep = 0; rep < 2; rep++) {
        int t = tid + rep * 128;
        int b = t >> 5, o = t & 31;
        int slot = ((b >> 1) * 8 + (o >> 2)) * 8 + (b & 1) * 4 + (o & 3);
        float sx = 0.0f, sy = 0.0f;
        #pragma unroll
        for (int ww = 0; ww < 4; ww++) {
            float lo, hi; upk(red[ww * 256 + slot], lo, hi);
            sx += lo; sy += hi;
        }
        g_zc[s * 256 + t] = make_float2(sx, sy);
    }
}

// ---------------- l-reduction with Wsy; ONLY ni >= 15 (Zsum Hermitian) --------
__global__ void k_zsum() {
    int mi = blockIdx.x >> 4;
    int ni = 15 + (blockIdx.x & 15);
    int m = mi - 15, n = ni - 15;
    int am = m < 0 ? -m : m;
    int lmin = am > n ? am : n;
    int nl = 16 - lmin;
    bool cano = (m >= 0);
    float sg = ((m - n) & 1) ? -1.0f : 1.0f;
    __shared__ u64 ws2[16 * 32];
    __shared__ int srowW[16];
    __shared__ int srowZ[16];
    int tid = threadIdx.x;
    if (tid < nl) {
        int l = lmin + tid, d = 2*l + 1;
        srowW[tid] = c_OFF[l] + (m + l) * d + (n + l);
        srowZ[tid] = cano ? srowW[tid] : c_OFF[l] + (l - m) * d + (l - n);
    }
    __syncthreads();
    for (int idx = tid; idx < nl * 32; idx += 256) {
        float w = g_Wsy[srowW[idx >> 5] * 32 + (idx & 31)];
        ws2[idx] = cano ? pk(w, w) : pk(w * sg, -w * sg);
    }
    __syncthreads();
    u64 acc[32];
    #pragma unroll
    for (int j = 0; j < 32; j++) acc[j] = 0ULL;
    for (int li = 0; li < nl; li++) {
        float2 z = g_zc[srowZ[li] * 256 + tid];
        u64 zp = pk(z.x, z.y);
        #pragma unroll
        for (int j = 0; j < 32; j++)
            acc[j] = fma2(zp, ws2[li * 32 + j], acc[j]);
    }
    int base = (mi * 31 + ni) * 8192 + tid;
    #pragma unroll
    for (int j = 0; j < 32; j++) {
        float lo, hi; upk(acc[j], lo, hi);
        g_Zsum[base + j * 256] = make_float2(lo, hi);
    }
}

// ---------------- inverse DFT over m-axis: ONLY ni >= 15 ----------------
__global__ void k_g1() {
    int bid = blockIdx.x;
    int half = bid & 1;
    int j = (bid >> 1) & 31;
    int ni = 15 + (bid >> 6);
    __shared__ __align__(16) float2 zin[31 * 128];
    __shared__ u64 twC2[16 * 16];
    __shared__ u64 twS2[16 * 16];
    int tid = threadIdx.x;
    for (int idx = tid; idx < 31 * 128; idx += 128)
        zin[idx] = g_Zsum[((idx >> 7) * 31 + ni) * 8192 + j * 256 + half * 128 + (idx & 127)];
    for (int idx = tid; idx < 256; idx += 128) {
        float c = g_tw16C[idx], s = g_tw16S[idx];
        twC2[idx] = pk(c, c);
        twS2[idx] = pk(s, s);
    }
    __syncthreads();
    u64 neg1 = pk(-1.0f, -1.0f);
    u64 one1 = pk(1.0f, 1.0f);
    u64 z0 = *(const u64*)&zin[15 * 128 + tid];
    u64 acc[32];
    #pragma unroll
    for (int a = 0; a < 32; a++) acc[a] = z0;
    for (int mm = 1; mm <= 15; mm++) {
        u64 zp = *(const u64*)&zin[(15 + mm) * 128 + tid];
        u64 zm = *(const u64*)&zin[(15 - mm) * 128 + tid];
        u64 U = add2(zp, zm);
        u64 V = fma2(zm, neg1, zp);
        float vx, vy; upk(V, vx, vy);
        u64 iV = pk(-vy, vx);
        u64 sg = (mm & 1) ? neg1 : one1;
        #pragma unroll
        for (int a = 0; a < 16; a++) {
            u64 p = fma2(twC2[a * 16 + mm], U, fma2(twS2[a * 16 + mm], iV, 0ULL));
            acc[a]      = add2(acc[a], p);
            acc[a + 16] = fma2(p, sg, acc[a + 16]);
        }
    }
    #pragma unroll
    for (int a = 0; a < 32; a++) {
        float lo, hi; upk(acc[a], lo, hi);
        g_U1[((a * 31 + ni) * 32 + j) * 256 + half * 128 + tid] = make_float2(lo, hi);
    }
}

// ---------------- inverse DFT over n-axis: U1(a,-n) = conj(U1(a,n)) ----------------
__global__ void k_g2(const float* __restrict__ bias, float* __restrict__ out) {
    int bid = blockIdx.x;
    int half = bid & 1;
    int j = (bid >> 1) & 31;
    int a = bid >> 6;
    __shared__ __align__(16) float2 uA[16 * 128];
    __shared__ u64 twA[16 * 8];
    __shared__ u64 twB[16 * 8];
    int tid = threadIdx.x;
    for (int idx = tid; idx < 16 * 128; idx += 128) {
        int k = idx >> 7, t = idx & 127;
        uA[idx] = g_U1[((a * 31 + 15 + k) * 32 + j) * 256 + half * 128 + t];
    }
    if (tid < 128) {
        int n = tid >> 3, q = tid & 7;
        twA[tid] = *(const u64*)&g_tw16C[n * 16 + 2 * q];
        twB[tid] = *(const u64*)&g_tw16S[n * 16 + 2 * q];
    }
    __syncthreads();
    u64 neg1 = pk(-1.0f, -1.0f);
    u64 one1 = pk(1.0f, 1.0f);
    int bo = half * 128 + tid;
    float bv = bias[bo & 31];
    float2 u0 = uA[tid];
    float base = bv + u0.x;
    u64 v2[16];
    #pragma unroll
    for (int q = 0; q < 16; q++) v2[q] = pk(base, base);
    for (int nn = 1; nn <= 15; nn++) {
        float2 up = uA[nn * 128 + tid];
        float Uv = 2.0f * up.x;
        float Vv = -2.0f * up.y;
        u64 U2 = pk(Uv, Uv), V2 = pk(Vv, Vv);
        u64 sg = (nn & 1) ? neg1 : one1;
        #pragma unroll
        for (int q = 0; q < 8; q++) {
            u64 p = fma2(twA[nn * 8 + q], U2, fma2(twB[nn * 8 + q], V2, 0ULL));
            v2[q]     = add2(v2[q], p);
            v2[q + 8] = fma2(p, sg, v2[q + 8]);
        }
    }
    float v[32];
    #pragma unroll
    for (int q = 0; q < 8; q++) {
        upk(v2[q], v[2*q], v[2*q + 1]);
        upk(v2[q + 8], v[16 + 2*q], v[17 + 2*q]);
    }
    float4* op = (float4*)(out + (long)bo * 32768 + a * 1024 + j * 32);
    #pragma unroll
    for (int q2 = 0; q2 < 8; q2++)
        op[q2] = make_float4(v[4*q2], v[4*q2+1], v[4*q2+2], v[4*q2+3]);
}

// ---------------- launch ----------------
extern "C" void kernel_launch(void* const* d_in, const int* in_sizes, int n_in,
                              void* d_out, int out_size) {
    const float* x    = (const float*)d_in[0];   // [8,16,64,64,64]
    const float* ker  = (const float*)d_in[1];   // [16,32,72]
    const float* bias = (const float*)d_in[2];   // [32]
    const float* ge   = (const float*)d_in[3];   // [72,3]
    float* out = (float*)d_out;                  // [8,32,32,32,32]

    k_init  <<<144, 256>>>(ker);
    k_wigner<<<NSPEC, 192>>>(ge);
    k_dftA  <<<4096, 256>>>(x);
    k_dftC  <<<2048, 256>>>();
    k_xc    <<<496, 128>>>();
    k_yc    <<<684, 512>>>();
    k_ze    <<<NSPEC, 128>>>();
    k_zsum  <<<496, 256>>>();
    k_g1    <<<1024, 128>>>();
    k_g2    <<<2048, 128>>>(bias, out);
}

// round 16
// speedup vs baseline: 1.0398x; 1.0398x over previous
#include <cuda_runtime.h>
#include <cuda_bf16.h>
#include <math.h>

// ---------------- constants ----------------
#define NSPEC 5456
#define PI_F 3.14159265358979323846f

__constant__ int c_OFF[17] = {0,1,10,35,84,165,286,455,680,969,1330,1771,2300,2925,3654,4495,5456};
// prefix of canonical-row counts per l:  cnt(l) = 2l^2+2l+1
__constant__ int c_POFF[17] = {0,1,6,19,44,85,146,231,344,489,670,891,1156,1469,1834,2255,2736};

// log(n!) for n = 0..31 (double; needed for cancellation-heavy Wigner coefficients)
__constant__ double c_LFD[32] = {
    0.0, 0.0, 0.6931471805599453, 1.791759469228055,
    3.1780538303479458, 4.787491742782046, 6.579251212010101, 8.525161361065415,
    10.60460290274525, 12.801827480081469, 15.104412573075516, 17.502307845873887,
    19.987214495661885, 22.552163853123425, 25.19122118273868, 27.89927138384089,
    30.671860106080672, 33.50507345013689, 36.39544520803305, 39.339884187199495,
    42.335616460753485, 45.38013889847691, 48.47118135183523, 51.60667556776438,
    54.78472939811232, 58.00360522298052, 61.261701761002, 64.55753862700634,
    67.88974313718154, 71.25703896716801, 74.65823978744394, 78.09222699192909
};

typedef unsigned long long u64;

// ---------------- f32x2 packed helpers ----------------
__device__ __forceinline__ u64 pk(float lo, float hi) {
    u64 r; asm("mov.b64 %0,{%1,%2};" : "=l"(r) : "f"(lo), "f"(hi)); return r;
}
__device__ __forceinline__ u64 fma2(u64 a, u64 b, u64 c) {
    u64 r; asm("fma.rn.f32x2 %0,%1,%2,%3;" : "=l"(r) : "l"(a), "l"(b), "l"(c)); return r;
}
__device__ __forceinline__ u64 add2(u64 a, u64 b) {
    u64 r; asm("add.rn.f32x2 %0,%1,%2;" : "=l"(r) : "l"(a), "l"(b)); return r;
}
__device__ __forceinline__ void upk(u64 v, float& lo, float& hi) {
    asm("mov.b64 {%0,%1},%2;" : "=f"(lo), "=f"(hi) : "l"(v));
}

// ---------------- scratch (static device globals; no allocation) ----------------
__device__ float2 g_T1[8388608];     // [bf=128][m=16][j=64][c=64]   (m >= 0 only)
__device__ float2 g_T2[7872512];     // [mi=31][ni=31][j=64][bf=128] (only mi>=15 written)
__device__ float  g_Wan[NSPEC*64];
__device__ float  g_Wsy[NSPEC*32];
__device__ float2 g_D[NSPEC*72];
__device__ float  g_wquad[64];
__device__ float  g_KT[72*512];
__device__ float  g_tw32C[512];      // [i<16][j<32] cos(i*j*pi/32)
__device__ float  g_tw32S[512];
__device__ float  g_tw16C[256];      // [i<16][j<16] cos(i*j*pi/16)
__device__ float  g_tw16S[256];
__device__ float2 g_xc[NSPEC*128];   // [s][b*16+f]   (only m>=0 rows written)
__device__ float2 g_yc[NSPEC*512];   // [s][i*32+o]
__device__ float2 g_zc[NSPEC*256];   // [s][b*32+o]   (only canonical s written)
__device__ float2 g_Zsum[7872512];   // [mi=31][ni=31][j=32][bo=256]  (only ni>=15 written)
__device__ float2 g_U1[8126464];     // [a=32][ni=31][j=32][bo=256]   (only ni>=15 written)

// ---------------- init: KT, quad weights, twiddle tables ----------------
__global__ void k_init(const float* __restrict__ ker) {
    int idx = blockIdx.x * blockDim.x + threadIdx.x;
    if (idx < 36864) {
        int g  = idx >> 9;
        int io = idx & 511;
        g_KT[idx] = ker[io * 72 + g] * (1.0f / 12.0f);
    }
    if (idx < 512) {
        int i = idx >> 5, j = idx & 31;
        float sv, cv; sincosf(0.0981747704f * (float)(i * j), &sv, &cv);  // pi/32
        g_tw32C[idx] = cv; g_tw32S[idx] = sv;
    }
    if (idx < 256) {
        int i = idx >> 4, j = idx & 15;
        float sv, cv; sincosf(0.1963495408f * (float)(i * j), &sv, &cv);  // pi/16
        g_tw16C[idx] = cv; g_tw16S[idx] = sv;
    }
    if (idx < 64) {
        int j = idx;
        float inner = 0.0f;
        for (int k = 0; k < 32; k++)
            inner += sinf((float)((2*j+1)*(2*k+1)) * PI_F / 128.0f) / (float)(2*k+1);
        float w = (2.0f / 32.0f) * sinf(PI_F * (float)(2*j+1) / 128.0f) * inner;
        g_wquad[j] = w / 4096.0f;
    }
}

// ---------------- Wigner tables: canonical (M,N) only; mirrors written via symmetry --------
__global__ void k_wigner(const float* __restrict__ ge) {
    int s = blockIdx.x;
    __shared__ float lcoef[32];
    int t = threadIdx.x;
    int l = 0;
    #pragma unroll
    for (int i = 1; i < 16; i++) l += (c_OFF[i] <= s) ? 1 : 0;
    int dsz = 2*l + 1;
    int rem = s - c_OFF[l];
    int M = rem / dsz - l;
    int N = rem % dsz - l;
    if (!(M > 0 || (M == 0 && N >= 0))) return;   // non-canonical: mirror handles it
    int smir = c_OFF[l] + (l - M) * dsz + (l - N);
    float sg = ((M - N) & 1) ? -1.0f : 1.0f;
    int Kmin = (M - N) > 0 ? (M - N) : 0;
    int Kmax = (l + M) < (l - N) ? (l + M) : (l - N);
    if (t < 32 && t >= Kmin && t <= Kmax) {
        double lgA = 0.5 * (c_LFD[l+M] + c_LFD[l-M] + c_LFD[l+N] + c_LFD[l-N]);
        lcoef[t] = (float)(lgA - (c_LFD[t] + c_LFD[l+M-t] + c_LFD[l-N-t] + c_LFD[N-M+t]));
    }
    __syncthreads();
    if (t >= 168) return;
    float beta;
    if (t < 64)       beta = PI_F * (float)(2*t + 1) / 128.0f;
    else if (t < 96)  beta = PI_F * (float)(2*(t-64) + 1) / 64.0f;
    else              beta = ge[(t - 96) * 3 + 1];
    float ch  = __cosf(0.5f * beta);
    float shv = __sinf(0.5f * beta);
    float lc  = __logf(ch);
    float lsn = __logf(shv);
    float dval = 0.0f;
    for (int K = Kmin; K <= Kmax; K++) {
        int e1 = 2*l + M - N - 2*K;
        int e2 = N - M + 2*K;
        float arg = lcoef[K];
        if (e1) arg += (float)e1 * lc;
        if (e2) arg += (float)e2 * lsn;
        float term = __expf(arg);
        dval += (K & 1) ? -term : term;
    }
    if (t < 64) {
        float wv = dval * g_wquad[t];
        g_Wan[s * 64 + t] = wv;
        if (M == 0 && s != smir)
            g_Wan[smir * 64 + t] = sg * wv;
    } else if (t < 96) {
        float wv = dval * (float)(2*l + 1);
        g_Wsy[s * 32 + (t - 64)] = wv;
        if (s != smir) g_Wsy[smir * 32 + (t - 64)] = sg * wv;
    } else {
        int g = t - 96;
        float alpha = ge[g*3 + 0], gamma = ge[g*3 + 2];
        float th = (float)M * alpha + (float)N * gamma;
        float sv, cv; __sincosf(th, &sv, &cv);
        float2 Dv = make_float2(dval * cv, -dval * sv);
        g_D[s * 72 + g] = Dv;
        if (s != smir) g_D[smir * 72 + g] = make_float2(sg * Dv.x, -sg * Dv.y);
    }
}

// ---------------- Stage A: DFT over first axis, a-folded (R14 version) ----------------
// block per (bf, j): 8192 blocks x 256 threads = (c 0..63) x (m0 0..3)
__global__ void k_dftA(const float* __restrict__ x) {
    __shared__ __align__(16) float sxu[64 * 36];
    __shared__ __align__(16) float sxv[64 * 36];
    __shared__ __align__(16) float twC[16 * 32];
    __shared__ __align__(16) float twS[16 * 32];
    int bid = blockIdx.x;
    int j = bid & 63, bf = bid >> 6;
    int tid = threadIdx.x;
    const float* xb = x + bf * 262144 + j * 64;
    for (int idx = tid; idx < 2048; idx += 256) {
        int a = idx >> 6, c = idx & 63;
        float xa = xb[a * 4096 + c];
        float xc2 = xb[(a + 32) * 4096 + c];
        sxu[c * 36 + a] = xa + xc2;
        sxv[c * 36 + a] = xa - xc2;
    }
    for (int idx = tid; idx < 512; idx += 256) {
        twC[idx] = g_tw32C[idx];
        twS[idx] = g_tw32S[idx];
    }
    __syncthreads();
    int c = tid & 63, m0 = tid >> 6;
    u64 aC[4] = {0ULL,0ULL,0ULL,0ULL}, aS[4] = {0ULL,0ULL,0ULL,0ULL};
    for (int a0 = 0; a0 < 32; a0 += 4) {
        ulonglong2 U = *(const ulonglong2*)&sxu[c * 36 + a0];
        ulonglong2 V = *(const ulonglong2*)&sxv[c * 36 + a0];
        #pragma unroll
        for (int it = 0; it < 4; it++) {
            int m = m0 * 4 + it;
            ulonglong2 TC = *(const ulonglong2*)&twC[m * 32 + a0];
            ulonglong2 TS = *(const ulonglong2*)&twS[m * 32 + a0];
            u64 xlo = (it & 1) ? V.x : U.x;
            u64 xhi = (it & 1) ? V.y : U.y;
            aC[it] = fma2(xlo, TC.x, aC[it]);
            aC[it] = fma2(xhi, TC.y, aC[it]);
            aS[it] = fma2(xlo, TS.x, aS[it]);
            aS[it] = fma2(xhi, TS.y, aS[it]);
        }
    }
    #pragma unroll
    for (int it = 0; it < 4; it++) {
        int m = m0 * 4 + it;
        float c1, c2, s1, s2;
        upk(aC[it], c1, c2); upk(aS[it], s1, s2);
        g_T1[bf * 65536 + m * 4096 + j * 64 + c] = make_float2(c1 + c2, -(s1 + s2));
    }
}

// ---------------- Stage C: DFT over third axis; ONLY mi >= 15 (m >= 0) ----
// grid: (mi-15)*128 + j*2 + bfh = 2048 blocks x 256 threads
__global__ void k_dftC() {
    __shared__ __align__(16) float suX[64 * 36];
    __shared__ __align__(16) float suY[64 * 36];
    __shared__ __align__(16) float svX[64 * 36];
    __shared__ __align__(16) float svY[64 * 36];
    __shared__ __align__(16) float twQC[16 * 32];
    __shared__ __align__(16) float twQS[16 * 32];
    int bid = blockIdx.x;
    int mi  = 15 + (bid >> 7);
    int j   = (bid >> 1) & 63;
    int bf0 = (bid & 1) * 64;
    int m = mi - 15;
    int tid = threadIdx.x;
    for (int idx = tid; idx < 2048; idx += 256) {
        int bfl = idx >> 5, c = idx & 31;
        const float2* p = &g_T1[(bf0 + bfl) * 65536 + m * 4096 + j * 64];
        float2 a = p[c];
        float2 b = p[c + 32];
        suX[bfl * 36 + c] = a.x + b.x;
        svX[bfl * 36 + c] = a.x - b.x;
        suY[bfl * 36 + c] = a.y + b.y;
        svY[bfl * 36 + c] = a.y - b.y;
    }
    for (int idx = tid; idx < 512; idx += 256) {
        twQC[idx] = g_tw32C[idx];
        twQS[idx] = g_tw32S[idx];
    }
    __syncthreads();
    int bfl = tid & 63, q0 = tid >> 6;
    const float* sX = (q0 & 1) ? svX : suX;
    const float* sY = (q0 & 1) ? svY : suY;
    u64 A[16];
    #pragma unroll
    for (int i = 0; i < 16; i++) A[i] = 0ULL;
    for (int c0 = 0; c0 < 32; c0 += 4) {
        ulonglong2 X = *(const ulonglong2*)&sX[bfl * 36 + c0];
        ulonglong2 Y = *(const ulonglong2*)&sY[bfl * 36 + c0];
        #pragma unroll
        for (int it = 0; it < 4; it++) {
            int q = q0 + 4 * it;
            ulonglong2 TC = *(const ulonglong2*)&twQC[q * 32 + c0];
            ulonglong2 TS = *(const ulonglong2*)&twQS[q * 32 + c0];
            A[it*4+0] = fma2(X.x, TC.x, A[it*4+0]);
            A[it*4+0] = fma2(X.y, TC.y, A[it*4+0]);
            A[it*4+1] = fma2(X.x, TS.x, A[it*4+1]);
            A[it*4+1] = fma2(X.y, TS.y, A[it*4+1]);
            A[it*4+2] = fma2(Y.x, TC.x, A[it*4+2]);
            A[it*4+2] = fma2(Y.y, TC.y, A[it*4+2]);
            A[it*4+3] = fma2(Y.x, TS.x, A[it*4+3]);
            A[it*4+3] = fma2(Y.y, TS.y, A[it*4+3]);
        }
    }
    #pragma unroll
    for (int it = 0; it < 4; it++) {
        int q = q0 + 4 * it;
        float a1, a2;
        float Sxc, SxS, Syc, SyS;
        upk(A[it*4+0], a1, a2); Sxc = a1 + a2;
        upk(A[it*4+1], a1, a2); SxS = a1 + a2;
        upk(A[it*4+2], a1, a2); Syc = a1 + a2;
        upk(A[it*4+3], a1, a2); SyS = a1 + a2;
        g_T2[((mi * 31 + (15 + q)) * 64 + j) * 128 + bf0 + bfl] =
            make_float2(Sxc + SyS, Syc - SxS);
        if (q > 0)
            g_T2[((mi * 31 + (15 - q)) * 64 + j) * 128 + bf0 + bfl] =
                make_float2(Sxc - SyS, Syc + SxS);
    }
}

// ---------------- xc: ONLY mi >= 15; block per (mi,ni) ----------------
__global__ void k_xc() {
    int mi = 15 + blockIdx.x / 31, ni = blockIdx.x % 31;
    int m = mi - 15, n = ni - 15;
    int an = n < 0 ? -n : n;
    int lmin = m > an ? m : an;
    int nl = 16 - lmin;
    __shared__ float ws[16 * 64];
    __shared__ int srow[16];
    int tid = threadIdx.x;
    if (tid < nl) {
        int l = lmin + tid;
        srow[tid] = c_OFF[l] + (m + l) * (2*l + 1) + (n + l);
    }
    __syncthreads();
    for (int idx = tid; idx < nl * 64; idx += 128)
        ws[idx] = g_Wan[srow[idx >> 6] * 64 + (idx & 63)];
    __syncthreads();
    u64 acc[16];
    #pragma unroll
    for (int i = 0; i < 16; i++) acc[i] = 0ULL;
    const float2* src = &g_T2[(mi * 31 + ni) * 8192 + tid];
    for (int j = 0; j < 64; j++) {
        float2 v = src[j * 128];
        u64 vp = pk(v.x, v.y);
        #pragma unroll
        for (int li = 0; li < 16; li++) {
            if (li < nl) {
                float w = ws[li * 64 + j];
                acc[li] = fma2(vp, pk(w, w), acc[li]);
            }
        }
    }
    #pragma unroll
    for (int li = 0; li < 16; li++) {
        if (li < nl) {
            float lo, hi; upk(acc[li], lo, hi);
            g_xc[srow[li] * 128 + tid] = make_float2(lo, hi);
        }
    }
}

// ---------------- yc: canonical rows only (compact grid) + mirror writes ----------------
__global__ void k_yc() {
    __shared__ __align__(16) float2 ds[4 * 72];
    __shared__ int   sS[4], sMir[4];
    __shared__ float sSg[4];
    int t = threadIdx.x;
    if (t < 4) {
        int cs = blockIdx.x * 4 + t;
        int l = 0;
        #pragma unroll
        for (int i = 1; i < 16; i++) l += (c_POFF[i] <= cs) ? 1 : 0;
        int r = cs - c_POFF[l];
        int d = 2 * l + 1;
        int M, N;
        if (r <= l) { M = 0; N = r; }
        else { int rr = r - (l + 1); M = rr / d + 1; N = rr % d - l; }
        sS[t]   = c_OFF[l] + (M + l) * d + (N + l);
        sMir[t] = c_OFF[l] + (l - M) * d + (l - N);
        sSg[t]  = ((M - N) & 1) ? -1.0f : 1.0f;
    }
    __syncthreads();
    if (t < 288) {
        int row = t / 72, g = t % 72;
        ds[t] = g_D[sS[row] * 72 + g];
    }
    __syncthreads();
    u64 a0 = 0ULL, a1 = 0ULL, a2 = 0ULL, a3 = 0ULL;
    #pragma unroll 4
    for (int g = 0; g < 72; g++) {
        float k = g_KT[g * 512 + t];
        u64 k2 = pk(k, k);
        a0 = fma2(k2, *(const u64*)&ds[g],       a0);
        a1 = fma2(k2, *(const u64*)&ds[72 + g],  a1);
        a2 = fma2(k2, *(const u64*)&ds[144 + g], a2);
        a3 = fma2(k2, *(const u64*)&ds[216 + g], a3);
    }
    u64 accs[4] = {a0, a1, a2, a3};
    #pragma unroll
    for (int row = 0; row < 4; row++) {
        float lo, hi; upk(accs[row], lo, hi);
        int s = sS[row], smir = sMir[row];
        g_yc[s * 512 + t] = make_float2(lo, hi);
        if (smir != s) {
            float sg = sSg[row];
            g_yc[smir * 512 + t] = make_float2(sg * lo, -sg * hi);
        }
    }
}

// ---------------- main block-diagonal complex GEMM: compact canonical grid (2736) ----------
__global__ void k_ze() {
    __shared__ __align__(16) unsigned char sraw[49152];
    ulonglong2* xch = (ulonglong2*)sraw;            //  8KB
    ulonglong2* ysh = (ulonglong2*)(sraw + 8192);   // 32KB
    u64*        red = (u64*)sraw;                   //  8KB (reuses xch)
    int cs = blockIdx.x;
    int tid = threadIdx.x;
    int w = tid >> 5, lane = tid & 31;
    int bg = lane >> 3, og = lane & 7;
    int l = 0;
    #pragma unroll
    for (int i = 1; i < 16; i++) l += (c_POFF[i] <= cs) ? 1 : 0;
    int d = 2 * l + 1;
    int r = cs - c_POFF[l];
    int M, N;
    if (r <= l) { M = 0; N = r; }
    else { int rr = r - (l + 1); M = rr / d + 1; N = rr % d - l; }
    int s = c_OFF[l] + (M + l) * d + (N + l);
    int xbase = c_OFF[l] + (M + l) * d;
    int ybase = c_OFF[l] + (N + l);
    u64 acc[8];
    #pragma unroll
    for (int i = 0; i < 8; i++) acc[i] = 0ULL;
    for (int k0 = 0; k0 < d; k0 += 4) {
        int kc = d - k0; if (kc > 4) kc = 4;
        if (k0) __syncthreads();
        for (int idx = tid; idx < kc * 128; idx += 128) {
            int kk = idx >> 7, rr2 = idx & 127;
            int i = rr2 & 15, b = rr2 >> 4;
            float2 v = g_xc[(xbase + k0 + kk) * 128 + rr2];
            xch[kk * 128 + i * 8 + b] = make_ulonglong2(pk(v.x, v.x), pk(-v.y, v.y));
        }
        for (int idx = tid; idx < kc * 512; idx += 128) {
            int kk = idx >> 9, t = idx & 511;
            float2 y = g_yc[(ybase + (k0 + kk) * d) * 512 + t];
            ysh[kk * 512 + t] = make_ulonglong2(pk(y.x, y.y), pk(y.y, y.x));
        }
        __syncthreads();
        if (w < kc) {
            const ulonglong2* xr = &xch[w * 128 + bg * 2];
            const ulonglong2* yr = &ysh[w * 512 + og * 4];
            #pragma unroll
            for (int i = 0; i < 16; i++) {
                ulonglong2 X0 = xr[i * 8];
                ulonglong2 X1 = xr[i * 8 + 1];
                ulonglong2 Y0 = yr[i * 32];
                ulonglong2 Y1 = yr[i * 32 + 1];
                ulonglong2 Y2 = yr[i * 32 + 2];
                ulonglong2 Y3 = yr[i * 32 + 3];
                acc[0] = fma2(X0.x, Y0.x, fma2(X0.y, Y0.y, acc[0]));
                acc[1] = fma2(X0.x, Y1.x, fma2(X0.y, Y1.y, acc[1]));
                acc[2] = fma2(X0.x, Y2.x, fma2(X0.y, Y2.y, acc[2]));
                acc[3] = fma2(X0.x, Y3.x, fma2(X0.y, Y3.y, acc[3]));
                acc[4] = fma2(X1.x, Y0.x, fma2(X1.y, Y0.y, acc[4]));
                acc[5] = fma2(X1.x, Y1.x, fma2(X1.y, Y1.y, acc[5]));
                acc[6] = fma2(X1.x, Y2.x, fma2(X1.y, Y2.y, acc[6]));
                acc[7] = fma2(X1.x, Y3.x, fma2(X1.y, Y3.y, acc[7]));
            }
        }
    }
    __syncthreads();
    #pragma unroll
    for (int i = 0; i < 8; i++) red[tid * 8 + i] = acc[i];
    __syncthreads();
    #pragma unroll
    for (int rep = 0; rep < 2; rep++) {
        int t = tid + rep * 128;
        int b = t >> 5, o = t & 31;
        int slot = ((b >> 1) * 8 + (o >> 2)) * 8 + (b & 1) * 4 + (o & 3);
        float sx = 0.0f, sy = 0.0f;
        #pragma unroll
        for (int ww = 0; ww < 4; ww++) {
            float lo, hi; upk(red[ww * 256 + slot], lo, hi);
            sx += lo; sy += hi;
        }
        g_zc[s * 256 + t] = make_float2(sx, sy);
    }
}

// ---------------- l-reduction with Wsy; ONLY ni >= 15 (Zsum Hermitian) --------
__global__ void k_zsum() {
    int mi = blockIdx.x >> 4;
    int ni = 15 + (blockIdx.x & 15);
    int m = mi - 15, n = ni - 15;
    int am = m < 0 ? -m : m;
    int lmin = am > n ? am : n;
    int nl = 16 - lmin;
    bool cano = (m >= 0);
    float sg = ((m - n) & 1) ? -1.0f : 1.0f;
    __shared__ u64 ws2[16 * 32];
    __shared__ int srowW[16];
    __shared__ int srowZ[16];
    int tid = threadIdx.x;
    if (tid < nl) {
        int l = lmin + tid, d = 2*l + 1;
        srowW[tid] = c_OFF[l] + (m + l) * d + (n + l);
        srowZ[tid] = cano ? srowW[tid] : c_OFF[l] + (l - m) * d + (l - n);
    }
    __syncthreads();
    for (int idx = tid; idx < nl * 32; idx += 256) {
        float w = g_Wsy[srowW[idx >> 5] * 32 + (idx & 31)];
        ws2[idx] = cano ? pk(w, w) : pk(w * sg, -w * sg);
    }
    __syncthreads();
    u64 acc[32];
    #pragma unroll
    for (int j = 0; j < 32; j++) acc[j] = 0ULL;
    for (int li = 0; li < nl; li++) {
        float2 z = g_zc[srowZ[li] * 256 + tid];
        u64 zp = pk(z.x, z.y);
        #pragma unroll
        for (int j = 0; j < 32; j++)
            acc[j] = fma2(zp, ws2[li * 32 + j], acc[j]);
    }
    int base = (mi * 31 + ni) * 8192 + tid;
    #pragma unroll
    for (int j = 0; j < 32; j++) {
        float lo, hi; upk(acc[j], lo, hi);
        g_Zsum[base + j * 256] = make_float2(lo, hi);
    }
}

// ---------------- inverse DFT over m-axis: ONLY ni >= 15 ----------------
__global__ void k_g1() {
    int bid = blockIdx.x;
    int half = bid & 1;
    int j = (bid >> 1) & 31;
    int ni = 15 + (bid >> 6);
    __shared__ __align__(16) float2 zin[31 * 128];
    __shared__ u64 twC2[16 * 16];
    __shared__ u64 twS2[16 * 16];
    int tid = threadIdx.x;
    for (int idx = tid; idx < 31 * 128; idx += 128)
        zin[idx] = g_Zsum[((idx >> 7) * 31 + ni) * 8192 + j * 256 + half * 128 + (idx & 127)];
    for (int idx = tid; idx < 256; idx += 128) {
        float c = g_tw16C[idx], s = g_tw16S[idx];
        twC2[idx] = pk(c, c);
        twS2[idx] = pk(s, s);
    }
    __syncthreads();
    u64 neg1 = pk(-1.0f, -1.0f);
    u64 one1 = pk(1.0f, 1.0f);
    u64 z0 = *(const u64*)&zin[15 * 128 + tid];
    u64 acc[32];
    #pragma unroll
    for (int a = 0; a < 32; a++) acc[a] = z0;
    for (int mm = 1; mm <= 15; mm++) {
        u64 zp = *(const u64*)&zin[(15 + mm) * 128 + tid];
        u64 zm = *(const u64*)&zin[(15 - mm) * 128 + tid];
        u64 U = add2(zp, zm);
        u64 V = fma2(zm, neg1, zp);
        float vx, vy; upk(V, vx, vy);
        u64 iV = pk(-vy, vx);
        u64 sg = (mm & 1) ? neg1 : one1;
        #pragma unroll
        for (int a = 0; a < 16; a++) {
            u64 p = fma2(twC2[a * 16 + mm], U, fma2(twS2[a * 16 + mm], iV, 0ULL));
            acc[a]      = add2(acc[a], p);
            acc[a + 16] = fma2(p, sg, acc[a + 16]);
        }
    }
    #pragma unroll
    for (int a = 0; a < 32; a++) {
        float lo, hi; upk(acc[a], lo, hi);
        g_U1[((a * 31 + ni) * 32 + j) * 256 + half * 128 + tid] = make_float2(lo, hi);
    }
}

// ---------------- inverse DFT over n-axis: U1(a,-n) = conj(U1(a,n)) ----------------
__global__ void k_g2(const float* __restrict__ bias, float* __restrict__ out) {
    int bid = blockIdx.x;
    int half = bid & 1;
    int j = (bid >> 1) & 31;
    int a = bid >> 6;
    __shared__ __align__(16) float2 uA[16 * 128];
    __shared__ u64 twA[16 * 8];
    __shared__ u64 twB[16 * 8];
    int tid = threadIdx.x;
    for (int idx = tid; idx < 16 * 128; idx += 128) {
        int k = idx >> 7, t = idx & 127;
        uA[idx] = g_U1[((a * 31 + 15 + k) * 32 + j) * 256 + half * 128 + t];
    }
    if (tid < 128) {
        int n = tid >> 3, q = tid & 7;
        twA[tid] = *(const u64*)&g_tw16C[n * 16 + 2 * q];
        twB[tid] = *(const u64*)&g_tw16S[n * 16 + 2 * q];
    }
    __syncthreads();
    u64 neg1 = pk(-1.0f, -1.0f);
    u64 one1 = pk(1.0f, 1.0f);
    int bo = half * 128 + tid;
    float bv = bias[bo & 31];
    float2 u0 = uA[tid];
    float base = bv + u0.x;
    u64 v2[16];
    #pragma unroll
    for (int q = 0; q < 16; q++) v2[q] = pk(base, base);
    for (int nn = 1; nn <= 15; nn++) {
        float2 up = uA[nn * 128 + tid];
        float Uv = 2.0f * up.x;
        float Vv = -2.0f * up.y;
        u64 U2 = pk(Uv, Uv), V2 = pk(Vv, Vv);
        u64 sg = (nn & 1) ? neg1 : one1;
        #pragma unroll
        for (int q = 0; q < 8; q++) {
            u64 p = fma2(twA[nn * 8 + q], U2, fma2(twB[nn * 8 + q], V2, 0ULL));
            v2[q]     = add2(v2[q], p);
            v2[q + 8] = fma2(p, sg, v2[q + 8]);
        }
    }
    float v[32];
    #pragma unroll
    for (int q = 0; q < 8; q++) {
        upk(v2[q], v[2*q], v[2*q + 1]);
        upk(v2[q + 8], v[16 + 2*q], v[17 + 2*q]);
    }
    float4* op = (float4*)(out + (long)bo * 32768 + a * 1024 + j * 32);
    #pragma unroll
    for (int q2 = 0; q2 < 8; q2++)
        op[q2] = make_float4(v[4*q2], v[4*q2+1], v[4*q2+2], v[4*q2+3]);
}

// ---------------- launch ----------------
extern "C" void kernel_launch(void* const* d_in, const int* in_sizes, int n_in,
                              void* d_out, int out_size) {
    const float* x    = (const float*)d_in[0];   // [8,16,64,64,64]
    const float* ker  = (const float*)d_in[1];   // [16,32,72]
    const float* bias = (const float*)d_in[2];   // [32]
    const float* ge   = (const float*)d_in[3];   // [72,3]
    float* out = (float*)d_out;                  // [8,32,32,32,32]

    k_init  <<<144, 256>>>(ker);
    k_wigner<<<NSPEC, 192>>>(ge);
    k_dftA  <<<8192, 256>>>(x);
    k_dftC  <<<2048, 256>>>();
    k_xc    <<<496, 128>>>();
    k_yc    <<<684, 512>>>();
    k_ze    <<<2736, 128>>>();
    k_zsum  <<<496, 256>>>();
    k_g1    <<<1024, 128>>>();
    k_g2    <<<2048, 128>>>(bias, out);
}